// round 1
// baseline (speedup 1.0000x reference)
#include <cuda_runtime.h>
#include <stdint.h>

// Problem constants (from reference)
#define MASS_H2O   18.01056f
#define MASS_NH3   17.02655f
#define MAX_MZ     30000
#define WINDOW     10
#define VOCAB      26
#define BATCH      32768
#define IONS       8

// total output elements = 32768 * 26 * 8 * 10 = 68,157,440  (divisible by 4)
#define TOTAL_ELEMS (BATCH * VOCAB * IONS * WINDOW)
#define TOTAL_VEC4  (TOTAL_ELEMS / 4)

__global__ __launch_bounds__(256)
void intensity_kernel(const float* __restrict__ spectrum,
                      const float* __restrict__ pepmass,
                      const float* __restrict__ prefix_mass,
                      const float* __restrict__ masses,
                      const int*   __restrict__ dir_ptr,
                      float* __restrict__ out)
{
    const int t = blockIdx.x * blockDim.x + threadIdx.x;
    if (t >= TOTAL_VEC4) return;

    const int dir = dir_ptr ? __ldg(dir_ptr) : 0;

    // element index of first of the 4 elements this thread handles
    const int e  = t * 4;
    // 80 elements per (b, v) group; a float4 never straddles a group (80 % 4 == 0)
    const int bv = e / 80;
    const int r  = e - bv * 80;          // position within the 80-element group
    const int b  = bv / VOCAB;
    const int v  = bv - b * VOCAB;

    const float pm = __ldg(pepmass     + b);
    const float pf = __ldg(prefix_mass + b);
    const float ms = __ldg(masses      + v);

    // direction == 0: cb = prefix + mass, cy = pep - cb
    // direction == 1: cy = prefix + mass, cb = pep - cy
    float cb, cy;
    if (dir == 0) { cb = pf + ms; cy = pm - cb; }
    else          { cy = pf + ms; cb = pm - cy; }

    // label mask: zero vocab rows {PAD=0, GO=1, EOS=2} (same set for both directions)
    const float lbl = (v >= 3) ? 1.0f : 0.0f;

    float4 o;
    float* op = &o.x;

    #pragma unroll
    for (int k = 0; k < 4; ++k) {
        const int rr  = r + k;           // 0..79
        const int ion = rr / 10;         // 0..7
        const int w   = rr - ion * 10;   // 0..9

        const float c = (ion < 4) ? cb : cy;
        const int   j = ion & 3;
        float m;
        if      (j == 1) m = c - MASS_H2O;
        else if (j == 2) m = c - MASS_NH3;
        else if (j == 3) m = c * 0.5f;
        else             m = c;

        // jnp.round = round-half-to-even; __float2int_rn matches exactly
        const int idx = __float2int_rn(m * 10.0f) - (WINDOW / 2);

        float val = 0.0f;
        if (idx >= 0 && idx <= (MAX_MZ - WINDOW)) {
            val = __ldg(spectrum + idx + w);
        }
        op[k] = val * lbl;
    }

    reinterpret_cast<float4*>(out)[t] = o;
}

extern "C" void kernel_launch(void* const* d_in, const int* in_sizes, int n_in,
                              void* d_out, int out_size)
{
    const float* spectrum    = (const float*)d_in[0];
    const float* pepmass     = (const float*)d_in[1];
    const float* prefix_mass = (const float*)d_in[2];
    const float* masses      = (const float*)d_in[3];
    const int*   dir_ptr     = (n_in >= 5) ? (const int*)d_in[4] : nullptr;
    float*       out         = (float*)d_out;

    const int threads = 256;
    const int blocks  = (TOTAL_VEC4 + threads - 1) / threads;   // 66,560 blocks
    intensity_kernel<<<blocks, threads>>>(spectrum, pepmass, prefix_mass,
                                          masses, dir_ptr, out);
}

// round 2
// speedup vs baseline: 1.1453x; 1.1453x over previous
#include <cuda_runtime.h>
#include <stdint.h>

// Problem constants (from reference)
#define MASS_H2O   18.01056f
#define MASS_NH3   17.02655f
#define MAX_MZ     30000
#define WINDOW     10
#define VOCAB      26
#define BATCH      32768
#define IONS       8

#define TOTAL_ELEMS (BATCH * VOCAB * IONS * WINDOW)   // 68,157,440
#define TOTAL_VEC4  (TOTAL_ELEMS / 4)                 // 17,039,360

#define GROUPS_PER_BLOCK 16
#define THREADS_PER_BLOCK 320        // 16 groups * 20 float4 each
#define NUM_BLOCKS ((BATCH * VOCAB) / GROUPS_PER_BLOCK)   // 53,248

__global__ __launch_bounds__(THREADS_PER_BLOCK)
void intensity_kernel(const float* __restrict__ spectrum,
                      const float* __restrict__ pepmass,
                      const float* __restrict__ prefix_mass,
                      const float* __restrict__ masses,
                      const int*   __restrict__ dir_ptr,
                      float* __restrict__ out)
{
    // per (local group, ion): .x = safe bin index, .y = float mask bits
    __shared__ int2 sii[GROUPS_PER_BLOCK * IONS + 2];   // +pad for base+1 read

    const int tid = threadIdx.x;

    // ---------------- Phase 1: compute 128 (group, ion) windows ----------
    if (tid < GROUPS_PER_BLOCK * IONS) {
        const int gl  = tid >> 3;          // local group 0..15
        const int ion = tid & 7;           // 0..7
        const int g   = blockIdx.x * GROUPS_PER_BLOCK + gl;
        const int b   = g / VOCAB;
        const int v   = g - b * VOCAB;

        const float pm = __ldg(pepmass     + b);
        const float pf = __ldg(prefix_mass + b);
        const float ms = __ldg(masses      + v);
        const int  dir = dir_ptr ? __ldg(dir_ptr) : 0;

        float cb, cy;
        if (dir == 0) { cb = pf + ms; cy = pm - cb; }
        else          { cy = pf + ms; cb = pm - cy; }

        const float c = (ion < 4) ? cb : cy;
        const int   j = ion & 3;
        // EXACT reference arithmetic: variant first (one rounding), then *10.
        float m;
        if      (j == 1) m = c - MASS_H2O;
        else if (j == 2) m = c - MASS_NH3;
        else if (j == 3) m = c * 0.5f;
        else             m = c;

        const int idx   = __float2int_rn(m * 10.0f) - (WINDOW / 2);
        const bool valid = (idx >= 0) && (idx <= MAX_MZ - WINDOW);
        const float mask = (valid && v >= 3) ? 1.0f : 0.0f;

        int2 p;
        p.x = valid ? idx : 0;             // safe base (loads stay in-bounds)
        p.y = __float_as_int(mask);
        sii[tid] = p;
    }
    __syncthreads();

    // ---------------- Phase 2: one float4 of output per thread -----------
    // float4 index within block = tid; global float4 = blockIdx*320 + tid
    const int gl = tid / 20;               // local group
    const int r4 = tid - gl * 20;          // quad within group, 0..19
    const int r  = r4 * 4;                 // first element offset in group, 0..76

    const int ion0 = r / 10;               // small-const division
    const int w0   = r - ion0 * 10;        // in {0,2,4,6,8}

    const int base = (gl << 3) + ion0;
    const int2 p0 = sii[base];             // LDS.64
    const int2 p1 = sii[base + 1];         // LDS.64 (padded; unused unless w0==8)
    const int   idx0 = p0.x,               idx1m10 = p1.x - 10;
    const float m0   = __int_as_float(p0.y), m1 = __int_as_float(p1.y);

    float4 o;
    float* op = &o.x;

    #pragma unroll
    for (int k = 0; k < 4; ++k) {
        const int  w  = w0 + k;            // 0..11
        const bool c2 = (w >= 10);         // crossed into next ion window
        const int  addr = (c2 ? idx1m10 : idx0) + w;
        const float msk = c2 ? m1 : m0;
        op[k] = __ldg(spectrum + addr) * msk;
    }

    const int i = blockIdx.x * THREADS_PER_BLOCK + tid;
    reinterpret_cast<float4*>(out)[i] = o;
}

extern "C" void kernel_launch(void* const* d_in, const int* in_sizes, int n_in,
                              void* d_out, int out_size)
{
    const float* spectrum    = (const float*)d_in[0];
    const float* pepmass     = (const float*)d_in[1];
    const float* prefix_mass = (const float*)d_in[2];
    const float* masses      = (const float*)d_in[3];
    const int*   dir_ptr     = (n_in >= 5) ? (const int*)d_in[4] : nullptr;
    float*       out         = (float*)d_out;

    intensity_kernel<<<NUM_BLOCKS, THREADS_PER_BLOCK>>>(
        spectrum, pepmass, prefix_mass, masses, dir_ptr, out);
}

// round 3
// speedup vs baseline: 1.1732x; 1.0244x over previous
#include <cuda_runtime.h>
#include <stdint.h>

// Problem constants (from reference)
#define MASS_H2O   18.01056f
#define MASS_NH3   17.02655f
#define MAX_MZ     30000
#define WINDOW     10
#define VOCAB      26
#define BATCH      32768
#define IONS       8

#define GROUPS_PER_BLOCK 16
#define ELEMS_PER_BLOCK  (GROUPS_PER_BLOCK * IONS * WINDOW)   // 1280
#define THREADS_PER_BLOCK 320                                  // 4 elems/thread
#define NUM_BLOCKS ((BATCH * VOCAB) / GROUPS_PER_BLOCK)        // 53,248

__global__ __launch_bounds__(THREADS_PER_BLOCK)
void intensity_kernel(const float* __restrict__ spectrum,
                      const float* __restrict__ pepmass,
                      const float* __restrict__ prefix_mass,
                      const float* __restrict__ masses,
                      const int*   __restrict__ dir_ptr,
                      float* __restrict__ out)
{
    // per block-local window (group*8 + ion): .x = safe bin index, .y = mask bits
    __shared__ int2 sii[GROUPS_PER_BLOCK * IONS];   // 128 entries, 1 KB

    const int tid = threadIdx.x;

    // ---------------- Phase 1: compute 128 (group, ion) windows ----------
    if (tid < GROUPS_PER_BLOCK * IONS) {
        const int gl  = tid >> 3;          // local group 0..15
        const int ion = tid & 7;           // 0..7
        const int g   = blockIdx.x * GROUPS_PER_BLOCK + gl;
        const int b   = g / VOCAB;
        const int v   = g - b * VOCAB;

        const float pm = __ldg(pepmass     + b);
        const float pf = __ldg(prefix_mass + b);
        const float ms = __ldg(masses      + v);
        const int  dir = dir_ptr ? __ldg(dir_ptr) : 0;

        float cb, cy;
        if (dir == 0) { cb = pf + ms; cy = pm - cb; }
        else          { cy = pf + ms; cb = pm - cy; }

        const float c = (ion < 4) ? cb : cy;
        const int   j = ion & 3;
        // EXACT reference arithmetic: variant first (one rounding), then *10.
        float m;
        if      (j == 1) m = c - MASS_H2O;
        else if (j == 2) m = c - MASS_NH3;
        else if (j == 3) m = c * 0.5f;
        else             m = c;

        const int idx    = __float2int_rn(m * 10.0f) - (WINDOW / 2);
        const bool valid = (idx >= 0) && (idx <= MAX_MZ - WINDOW);
        const float mask = (valid && v >= 3) ? 1.0f : 0.0f;

        int2 p;
        p.x = valid ? idx : 0;             // safe base (loads stay in-bounds)
        p.y = __float_as_int(mask);
        sii[tid] = p;
    }
    __syncthreads();

    // ---------------- Phase 2: lane-consecutive elements -----------------
    // Thread handles elements tid + 320k (k=0..3). For each k, the warp's
    // lanes read CONSECUTIVE gather addresses (minimal L1 sectors) and write
    // CONSECUTIVE output addresses (fully coalesced STG.32).
    const int blockbase = blockIdx.x * ELEMS_PER_BLOCK;

    #pragma unroll
    for (int k = 0; k < 4; ++k) {
        const int f = tid + k * THREADS_PER_BLOCK;          // 0..1279
        const unsigned win = (unsigned)f / 10u;             // block-local window
        const int w = f - (int)win * 10;                    // 0..9
        const int2 p = sii[win];                            // LDS.64 (near-broadcast)
        const float val = __ldg(spectrum + p.x + w) * __int_as_float(p.y);
        out[blockbase + f] = val;
    }
}

extern "C" void kernel_launch(void* const* d_in, const int* in_sizes, int n_in,
                              void* d_out, int out_size)
{
    const float* spectrum    = (const float*)d_in[0];
    const float* pepmass     = (const float*)d_in[1];
    const float* prefix_mass = (const float*)d_in[2];
    const float* masses      = (const float*)d_in[3];
    const int*   dir_ptr     = (n_in >= 5) ? (const int*)d_in[4] : nullptr;
    float*       out         = (float*)d_out;

    intensity_kernel<<<NUM_BLOCKS, THREADS_PER_BLOCK>>>(
        spectrum, pepmass, prefix_mass, masses, dir_ptr, out);
}

// round 4
// speedup vs baseline: 1.4009x; 1.1941x over previous
#include <cuda_runtime.h>
#include <stdint.h>

// Problem constants (from reference)
#define MASS_H2O   18.01056f
#define MASS_NH3   17.02655f
#define MAX_MZ     30000
#define WINDOW     10
#define VOCAB      26
#define BATCH      32768
#define IONS       8

#define TOTAL_GROUPS   (BATCH * VOCAB)          // 851,968
#define TILE_GROUPS    256
#define NUM_TILES      (TOTAL_GROUPS / TILE_GROUPS)   // 3328 exactly
#define WINDOWS_PER_TILE (TILE_GROUPS * IONS)         // 2048
#define ELEMS_PER_TILE   (WINDOWS_PER_TILE * WINDOW)  // 20480
#define THREADS        1024
#define ELEMS_PER_THREAD (ELEMS_PER_TILE / THREADS)   // 20

#define SPEC_FLOATS_PAD 30016                   // 30000 padded to 16B multiple
#define SPEC_BYTES      (SPEC_FLOATS_PAD * 4)   // 120,064
#define META_BYTES      (2 * WINDOWS_PER_TILE * 8)   // 32,768 (double buffer)
#define SMEM_BYTES      (SPEC_BYTES + META_BYTES)    // 152,832

#define GRID_BLOCKS 152

__global__ void __launch_bounds__(THREADS, 1)
intensity_kernel(const float* __restrict__ spectrum,
                 const float* __restrict__ pepmass,
                 const float* __restrict__ prefix_mass,
                 const float* __restrict__ masses,
                 const int*   __restrict__ dir_ptr,
                 float* __restrict__ out)
{
    extern __shared__ unsigned char smem_raw[];
    float* spec   = reinterpret_cast<float*>(smem_raw);
    int2*  winbuf = reinterpret_cast<int2*>(smem_raw + SPEC_BYTES);

    const int tid = threadIdx.x;

    // ---- one-time: stage the full spectrum into SMEM (30000/4 = 7500 float4)
    {
        const float4* s4 = reinterpret_cast<const float4*>(spectrum);
        float4*       d4 = reinterpret_cast<float4*>(spec);
        #pragma unroll 2
        for (int i = tid; i < MAX_MZ / 4; i += THREADS)
            d4[i] = s4[i];
    }
    const int dir = dir_ptr ? __ldg(dir_ptr) : 0;
    __syncthreads();

    int parity = 0;
    for (int tile = blockIdx.x; tile < NUM_TILES; tile += GRID_BLOCKS) {
        int2* wb = winbuf + parity * WINDOWS_PER_TILE;
        parity ^= 1;

        // ---------- Phase 1: 2048 windows, 2 per thread ----------
        #pragma unroll
        for (int j = 0; j < 2; ++j) {
            const int wi  = tid + j * THREADS;       // 0..2047
            const int gl  = wi >> 3;                 // local group
            const int ion = wi & 7;
            const int g   = tile * TILE_GROUPS + gl;
            const int b   = g / VOCAB;
            const int v   = g - b * VOCAB;

            const float pm = __ldg(pepmass     + b);
            const float pf = __ldg(prefix_mass + b);
            const float ms = __ldg(masses      + v);

            float cb, cy;
            if (dir == 0) { cb = pf + ms; cy = pm - cb; }
            else          { cy = pf + ms; cb = pm - cy; }

            const float c = (ion < 4) ? cb : cy;
            const int   jj = ion & 3;
            // EXACT reference arithmetic: variant first, then *10.
            float m;
            if      (jj == 1) m = c - MASS_H2O;
            else if (jj == 2) m = c - MASS_NH3;
            else if (jj == 3) m = c * 0.5f;
            else              m = c;

            const int  idx   = __float2int_rn(m * 10.0f) - (WINDOW / 2);
            const bool valid = (idx >= 0) && (idx <= MAX_MZ - WINDOW);
            const float mask = (valid && v >= 3) ? 1.0f : 0.0f;

            int2 p;
            p.x = valid ? idx : 0;
            p.y = __float_as_int(mask);
            wb[wi] = p;
        }

        // single barrier per tile: also separates last tile's phase-2 reads
        // (other buffer) from this buffer's upcoming reuse two tiles later.
        __syncthreads();

        // ---------- Phase 2: lane-consecutive elements, SMEM gather ----------
        float* outp = out + tile * ELEMS_PER_TILE + tid;
        #pragma unroll 5
        for (int k = 0; k < ELEMS_PER_THREAD; ++k) {
            const int f = tid + k * THREADS;               // 0..20479
            const unsigned win = (unsigned)f / 10u;
            const int w = f - (int)win * 10;
            const int2 p = wb[win];                        // LDS.64, near-broadcast
            outp[k * THREADS] = spec[p.x + w] * __int_as_float(p.y);
        }
        // no trailing sync: double-buffered metadata
    }
}

extern "C" void kernel_launch(void* const* d_in, const int* in_sizes, int n_in,
                              void* d_out, int out_size)
{
    const float* spectrum    = (const float*)d_in[0];
    const float* pepmass     = (const float*)d_in[1];
    const float* prefix_mass = (const float*)d_in[2];
    const float* masses      = (const float*)d_in[3];
    const int*   dir_ptr     = (n_in >= 5) ? (const int*)d_in[4] : nullptr;
    float*       out         = (float*)d_out;

    static bool attr_set = false;   // idempotent attribute, safe & deterministic
    cudaFuncSetAttribute(intensity_kernel,
                         cudaFuncAttributeMaxDynamicSharedMemorySize, SMEM_BYTES);

    intensity_kernel<<<GRID_BLOCKS, THREADS, SMEM_BYTES>>>(
        spectrum, pepmass, prefix_mass, masses, dir_ptr, out);
    (void)attr_set;
}

// round 5
// speedup vs baseline: 1.6052x; 1.1458x over previous
#include <cuda_runtime.h>
#include <stdint.h>

// Problem constants (from reference)
#define MASS_H2O   18.01056f
#define MASS_NH3   17.02655f
#define MAX_MZ     30000
#define WINDOW     10
#define VOCAB      26
#define BATCH      32768
#define IONS       8

#define TOTAL_GROUPS     (BATCH * VOCAB)               // 851,968
#define TILE_GROUPS      256
#define NUM_TILES        (TOTAL_GROUPS / TILE_GROUPS)  // 3328 exactly
#define WINDOWS_PER_TILE (TILE_GROUPS * IONS)          // 2048
#define ELEMS_PER_TILE   (WINDOWS_PER_TILE * WINDOW)   // 20480
#define VEC4_PER_TILE    (ELEMS_PER_TILE / 4)          // 5120
#define THREADS          1024
#define VEC4_PER_THREAD  (VEC4_PER_TILE / THREADS)     // 5

#define SPEC_FLOATS_PAD  30016                  // 30000 + 16 zero pad
#define SPEC_BYTES       (SPEC_FLOATS_PAD * 4)  // 120,064
#define METABUF          (WINDOWS_PER_TILE + 4) // +pad for win0+1 read
#define META_BYTES       (2 * METABUF * 4)      // double buffer, 16,416
#define SMEM_BYTES       (SPEC_BYTES + META_BYTES)

#define ZERO_IDX   30000                        // points at zero pad
#define GRID_BLOCKS 152

__global__ void __launch_bounds__(THREADS, 1)
intensity_kernel(const float* __restrict__ spectrum,
                 const float* __restrict__ pepmass,
                 const float* __restrict__ prefix_mass,
                 const float* __restrict__ masses,
                 const int*   __restrict__ dir_ptr,
                 float* __restrict__ out)
{
    extern __shared__ unsigned char smem_raw[];
    float* spec = reinterpret_cast<float*>(smem_raw);
    int*   meta = reinterpret_cast<int*>(smem_raw + SPEC_BYTES);

    const int tid = threadIdx.x;

    // ---- one-time: stage spectrum into SMEM, zero the pad region ----
    {
        const float4* s4 = reinterpret_cast<const float4*>(spectrum);
        float4*       d4 = reinterpret_cast<float4*>(spec);
        const float4  z4 = make_float4(0.f, 0.f, 0.f, 0.f);
        #pragma unroll 2
        for (int i = tid; i < SPEC_FLOATS_PAD / 4; i += THREADS)
            d4[i] = (i < MAX_MZ / 4) ? s4[i] : z4;
    }
    const int dir = dir_ptr ? __ldg(dir_ptr) : 0;
    __syncthreads();

    int parity = 0;
    for (int tile = blockIdx.x; tile < NUM_TILES; tile += GRID_BLOCKS) {
        int* mb = meta + parity * METABUF;
        parity ^= 1;

        // ---------- Phase 1: 2048 windows, 2 per thread ----------
        #pragma unroll
        for (int j = 0; j < 2; ++j) {
            const int wi  = tid + j * THREADS;       // 0..2047
            const int gl  = wi >> 3;
            const int ion = wi & 7;
            const int g   = tile * TILE_GROUPS + gl;
            const int b   = g / VOCAB;
            const int v   = g - b * VOCAB;

            const float pm = __ldg(pepmass     + b);
            const float pf = __ldg(prefix_mass + b);
            const float ms = __ldg(masses      + v);

            float cb, cy;
            if (dir == 0) { cb = pf + ms; cy = pm - cb; }
            else          { cy = pf + ms; cb = pm - cy; }

            const float c  = (ion < 4) ? cb : cy;
            const int   jj = ion & 3;
            // EXACT reference arithmetic: variant first, then *10.
            float m;
            if      (jj == 1) m = c - MASS_H2O;
            else if (jj == 2) m = c - MASS_NH3;
            else if (jj == 3) m = c * 0.5f;
            else              m = c;

            const int  idx   = __float2int_rn(m * 10.0f) - (WINDOW / 2);
            const bool keep  = (idx >= 0) && (idx <= MAX_MZ - WINDOW) && (v >= 3);
            mb[wi] = keep ? idx : ZERO_IDX;          // masked -> zero pad
        }
        __syncthreads();

        // ---------- Phase 2: 5 float4 per thread, SMEM gather ----------
        float4* out4 = reinterpret_cast<float4*>(out) + tile * VEC4_PER_TILE;

        #pragma unroll
        for (int k = 0; k < VEC4_PER_THREAD; ++k) {
            const int q  = tid + k * THREADS;        // float4 index, 0..5119
            const int e  = q * 4;                    // first element, e%10 even
            const unsigned win0 = (unsigned)e / 10u;
            const int w0 = e - (int)win0 * 10;       // in {0,2,4,6,8}

            const int m0 = mb[win0];
            const int m1 = mb[win0 + 1];             // pad entry keeps this safe
            const bool cross = (w0 == 8);            // only case a f4 straddles

            float4 o;
            o.x = spec[m0 + w0];
            o.y = spec[m0 + w0 + 1];
            const int a2 = cross ? m1     : m0 + w0 + 2;
            const int a3 = cross ? m1 + 1 : m0 + w0 + 3;
            o.z = spec[a2];
            o.w = spec[a3];

            out4[q] = o;
        }
        // no trailing sync: double-buffered metadata
    }
}

extern "C" void kernel_launch(void* const* d_in, const int* in_sizes, int n_in,
                              void* d_out, int out_size)
{
    const float* spectrum    = (const float*)d_in[0];
    const float* pepmass     = (const float*)d_in[1];
    const float* prefix_mass = (const float*)d_in[2];
    const float* masses      = (const float*)d_in[3];
    const int*   dir_ptr     = (n_in >= 5) ? (const int*)d_in[4] : nullptr;
    float*       out         = (float*)d_out;

    cudaFuncSetAttribute(intensity_kernel,
                         cudaFuncAttributeMaxDynamicSharedMemorySize, SMEM_BYTES);

    intensity_kernel<<<GRID_BLOCKS, THREADS, SMEM_BYTES>>>(
        spectrum, pepmass, prefix_mass, masses, dir_ptr, out);
}